// round 10
// baseline (speedup 1.0000x reference)
#include <cuda_runtime.h>
#include <cuda_bf16.h>
#include <math.h>

// ---------------------------------------------------------------------------
// ModelAndLoss: CE(output, target) + 0.1 * sum of pairwise CKA over two
// feature groups. Output layout: [loss, output(64*1000)] fp32.
// Shapes: output [64,1000] f32, target [64] i64-or-i32, feats_a [3,64,65536],
// feats_b [4,64,32768] f32.
//
// Gram kernel exploits symmetry (SYRK-style): warps 0-3 compute the 120
// strictly-upper 4x4 tiles on even 64-col stages, warps 4-7 compute the same
// tiles on odd stages (stored transposed), 16 spare lanes own the 16 diagonal
// tiles on all stages. Reduce folds P[a,b]+P[b,a] for cross-tile entries.
// ---------------------------------------------------------------------------

#define NROW 64
#define NF   7
#define NBLK 1280               // 768 (A: 3x256 chunks) + 512 (B: 4x128 chunks)

__device__ float g_part[(long long)NBLK * NROW * NROW];  // per-block partial grams
__device__ float g_gram[NF][NROW * NROW];
__device__ float g_ce;

// ---- packed f32x2 helpers (Blackwell FFMA2 path) --------------------------
__device__ __forceinline__ unsigned long long pack2(float lo, float hi) {
    unsigned long long r;
    asm("mov.b64 %0, {%1, %2};" : "=l"(r) : "f"(lo), "f"(hi));
    return r;
}
__device__ __forceinline__ unsigned long long ffma2(unsigned long long a,
                                                    unsigned long long b,
                                                    unsigned long long c) {
    unsigned long long d;
    asm("fma.rn.f32x2 %0, %1, %2, %3;" : "=l"(d) : "l"(a), "l"(b), "l"(c));
    return d;
}
__device__ __forceinline__ void unpack2(unsigned long long v, float& lo, float& hi) {
    asm("mov.b64 {%0, %1}, %2;" : "=f"(lo), "=f"(hi) : "l"(v));
}

// ---- Gram partial kernel --------------------------------------------------
__global__ __launch_bounds__(256) void gram_kernel(const float* __restrict__ A,
                                                   const float* __restrict__ B) {
    __shared__ __align__(16) float Xs[2][64][68];   // 34,816 B ping-pong

    const int bid = blockIdx.x;
    const float* Xp;
    long long D, c0;
    if (bid < 768) {                       // group A: 3 grams x 256 chunks
        int f  = bid >> 8;
        int ch = bid & 255;
        Xp = A + (long long)f * NROW * 65536;
        D  = 65536; c0 = (long long)ch * 256;
    } else {                               // group B: 4 grams x 128 chunks
        int rel = bid - 768;
        int f  = rel >> 7;
        int ch = rel & 127;
        Xp = B + (long long)f * NROW * 32768;
        D  = 32768; c0 = (long long)ch * 256;
    }

    const int tid = threadIdx.x;
    const int t7  = tid & 127;             // position within half-group
    const bool grpE = (tid < 128);         // even-stage group
    const bool diag = (t7 >= 120);

    // tile coordinates: diag lanes -> (d,d); others -> strictly-upper (i<j)
    int ti, tj;
    if (diag) {
        int d = (t7 - 120) + (grpE ? 0 : 8);
        ti = tj = d;
    } else {
        int i = 0, rem = t7;               // row i has (15-i) strict-upper tiles
        while (rem >= 15 - i) { rem -= 15 - i; ++i; }
        ti = i; tj = i + 1 + rem;
    }
    const int i0 = ti * 4, j0 = tj * 4;

    unsigned long long acc[4][2];
    #pragma unroll
    for (int u = 0; u < 4; ++u) { acc[u][0] = 0ull; acc[u][1] = 0ull; }

    float4 pre[4];
    // stage s covers columns [c0 + 64 s, c0 + 64 s + 64)
    #define LDG_STAGE(s)                                                     \
        {                                                                    \
            const long long cs = c0 + (s) * 64;                              \
            _Pragma("unroll")                                                \
            for (int t = 0; t < 4; ++t) {                                    \
                int lin = tid + 256 * t;                                     \
                int row = lin >> 4, q = lin & 15;                            \
                pre[t] = *(const float4*)(Xp + (long long)row * D + cs + 4 * q); \
            }                                                                \
        }
    #define STS_STAGE(p)                                                     \
        {                                                                    \
            _Pragma("unroll")                                                \
            for (int t = 0; t < 4; ++t) {                                    \
                int lin = tid + 256 * t;                                     \
                int row = lin >> 4, q = lin & 15;                            \
                Xs[p][4 * q + 0][row] = pre[t].x;                            \
                Xs[p][4 * q + 1][row] = pre[t].y;                            \
                Xs[p][4 * q + 2][row] = pre[t].z;                            \
                Xs[p][4 * q + 3][row] = pre[t].w;                            \
            }                                                                \
        }

    LDG_STAGE(0);
    STS_STAGE(0);
    __syncthreads();

    #pragma unroll
    for (int s = 0; s < 4; ++s) {
        const int cur = s & 1;
        if (s < 3) LDG_STAGE(s + 1);       // prefetch next stage into regs

        // grpE computes even stages, grpO odd stages, diag lanes all stages.
        if (diag || (grpE == ((s & 1) == 0))) {
            #pragma unroll 8
            for (int k = 0; k < 64; ++k) {
                const float4 av = *(const float4*)&Xs[cur][k][i0];
                const float4 bv = *(const float4*)&Xs[cur][k][j0];
                const unsigned long long b01 = pack2(bv.x, bv.y);
                const unsigned long long b23 = pack2(bv.z, bv.w);
                unsigned long long a;
                a = pack2(av.x, av.x);
                acc[0][0] = ffma2(a, b01, acc[0][0]);
                acc[0][1] = ffma2(a, b23, acc[0][1]);
                a = pack2(av.y, av.y);
                acc[1][0] = ffma2(a, b01, acc[1][0]);
                acc[1][1] = ffma2(a, b23, acc[1][1]);
                a = pack2(av.z, av.z);
                acc[2][0] = ffma2(a, b01, acc[2][0]);
                acc[2][1] = ffma2(a, b23, acc[2][1]);
                a = pack2(av.w, av.w);
                acc[3][0] = ffma2(a, b01, acc[3][0]);
                acc[3][1] = ffma2(a, b23, acc[3][1]);
            }
        }

        if (s < 3) {
            __syncthreads();               // all reads of other buf done
            STS_STAGE(1 - cur);            // write next stage
            __syncthreads();               // visible before next compute
        }
    }
    #undef LDG_STAGE
    #undef STS_STAGE

    // store partial tile: grpE upper in place; grpO transposed into lower
    // triangle; diag tiles in place (complete over all stages).
    float* P = g_part + (long long)bid * (NROW * NROW);
    #pragma unroll
    for (int u = 0; u < 4; ++u) {
        #pragma unroll
        for (int p = 0; p < 2; ++p) {
            float lo, hi;
            unpack2(acc[u][p], lo, hi);
            const int a = i0 + u;
            const int b0 = j0 + 2 * p;
            if (diag || grpE) {
                P[a * NROW + b0]     = lo;
                P[a * NROW + b0 + 1] = hi;
            } else {
                P[b0 * NROW + a]       = lo;
                P[(b0 + 1) * NROW + a] = hi;
            }
        }
    }
}

// ---- Reduce partials into g_gram (fold symmetric halves, no atomics) ------
__global__ void reduce_kernel() {
    int e = blockIdx.x * 256 + threadIdx.x;          // 0 .. 28671
    int f = e >> 12, entry = e & 4095;
    int a = entry >> 6, b = entry & 63;
    int base, cnt;
    if (f < 3) { base = f * 256;             cnt = 256; }
    else       { base = 768 + (f - 3) * 128; cnt = 128; }
    const float* p = g_part + (long long)base * 4096;
    float s = 0.0f;
    if ((a >> 2) == (b >> 2)) {            // same 4x4 diagonal tile: in place
        #pragma unroll 4
        for (int c = 0; c < cnt; ++c) s += p[(long long)c * 4096 + entry];
    } else {                               // cross tile: fold both halves
        int entryT = b * 64 + a;
        #pragma unroll 4
        for (int c = 0; c < cnt; ++c)
            s += p[(long long)c * 4096 + entry] + p[(long long)c * 4096 + entryT];
    }
    g_gram[f][entry] = s;
}

// ---- Cross-entropy: single block, warp-per-row, dtype-agnostic target -----
// Detects int32 vs int64 targets: for int64 data the odd 32-bit words (high
// halves) of the first 32 values are all zero; for int32 data they are actual
// class indices (all-zero with probability ~0). Reads at most 256 bytes, safe
// under either layout.
__global__ void ce_kernel(const float* __restrict__ x,
                          const void* __restrict__ tgt_raw) {
    __shared__ float rowloss[NROW];
    __shared__ int is64;
    const int w = threadIdx.x >> 5, lane = threadIdx.x & 31;

    if (threadIdx.x == 0) {
        const int* t32 = (const int*)tgt_raw;
        int odd_or = 0;
        for (int i = 1; i < 64; i += 2) odd_or |= t32[i];
        is64 = (odd_or == 0);
    }
    __syncthreads();

    for (int row = w; row < NROW; row += 8) {
        const float* xr = x + row * 1000;
        float m = -1e30f;
        for (int c = lane; c < 1000; c += 32) m = fmaxf(m, xr[c]);
        for (int off = 16; off; off >>= 1)
            m = fmaxf(m, __shfl_xor_sync(0xffffffffu, m, off));
        float s = 0.0f;
        for (int c = lane; c < 1000; c += 32) s += expf(xr[c] - m);
        for (int off = 16; off; off >>= 1)
            s += __shfl_xor_sync(0xffffffffu, s, off);
        if (lane == 0) {
            int t = is64 ? (int)((const long long*)tgt_raw)[row]
                         : ((const int*)tgt_raw)[row];
            rowloss[row] = (m + logf(s)) - xr[t];
        }
    }
    __syncthreads();
    if (threadIdx.x == 0) {
        float t = 0.0f;
        for (int r = 0; r < NROW; ++r) t += rowloss[r];
        g_ce = t / 64.0f;
    }
}

// ---- Finalize: HSIC/CKA from grams, write loss ----------------------------
__global__ void finalize_kernel(float* __restrict__ dst, int out_size) {
    __shared__ float r[NF][NROW];     // row sums (diag excluded)
    __shared__ double trkl[NF][NF];
    __shared__ double red[256];
    const int tid = threadIdx.x;

    for (int t = tid; t < NF * NROW; t += 256) {
        int f = t / NROW, a = t % NROW;
        const float* G = g_gram[f];
        float s = 0.0f;
        for (int b = 0; b < NROW; ++b)
            if (b != a) s += G[a * NROW + b];
        r[f][a] = s;
    }
    __syncthreads();

    for (int p = 0; p < NF * NF; ++p) {
        int i = p / NF, j = p % NF;
        bool same = (i < 3 && j < 3) || (i >= 3 && j >= 3);
        if (!same || j < i) continue;
        const float* Gi = g_gram[i];
        const float* Gj = g_gram[j];
        double sum = 0.0;
        for (int idx = tid; idx < NROW * NROW; idx += 256) {
            int a = idx >> 6, b = idx & 63;
            if (a != b) sum += (double)Gi[idx] * (double)Gj[idx];
        }
        red[tid] = sum; __syncthreads();
        for (int s = 128; s > 0; s >>= 1) {
            if (tid < s) red[tid] += red[tid + s];
            __syncthreads();
        }
        if (tid == 0) trkl[i][j] = red[0];
        __syncthreads();
    }

    if (tid == 0) {
        double s[NF];
        for (int f = 0; f < NF; ++f) {
            double ss = 0.0;
            for (int a = 0; a < NROW; ++a) ss += (double)r[f][a];
            s[f] = ss;
        }
        auto hsic = [&](int i, int j) -> double {
            double rr = 0.0;
            for (int a = 0; a < NROW; ++a) rr += (double)r[i][a] * (double)r[j][a];
            double t = (i <= j) ? trkl[i][j] : trkl[j][i];
            return (t + s[i] * s[j] / 3906.0 - 2.0 * rr / 62.0) / 3904.0;
        };
        double cka = 0.0;
        double d[NF];
        for (int f = 0; f < NF; ++f) d[f] = sqrt(hsic(f, f));
        for (int i = 0; i < 3; ++i)
            for (int j = 0; j < 3; ++j)
                cka += hsic(i, j) / (d[i] * d[j]);
        for (int i = 3; i < NF; ++i)
            for (int j = 3; j < NF; ++j)
                cka += hsic(i, j) / (d[i] * d[j]);

        float loss = g_ce + 0.1f * (float)cka;
        if (out_size > 64000) dst[0] = loss;
    }
}

// ---- echo the logits into the output buffer -------------------------------
__global__ void copy_kernel(const float* __restrict__ src, float* __restrict__ dst,
                            int n) {
    int i = blockIdx.x * 256 + threadIdx.x;
    if (i < n) dst[i] = src[i];
}

extern "C" void kernel_launch(void* const* d_in, const int* in_sizes, int n_in,
                              void* d_out, int out_size) {
    const float* outp = (const float*)d_in[0];
    const void*  tgt  = (const void*)d_in[1];
    const float* fa   = (const float*)d_in[2];
    const float* fb   = (const float*)d_in[3];
    float* dst = (float*)d_out;

    gram_kernel<<<NBLK, 256>>>(fa, fb);
    reduce_kernel<<<112, 256>>>();
    ce_kernel<<<1, 256>>>(outp, tgt);

    int off = out_size - 64000;
    if (off < 0) off = 0;
    copy_kernel<<<(64000 + 255) / 256, 256>>>(outp, dst + off, 64000);
    finalize_kernel<<<1, 256>>>(dst, out_size);
}

// round 13
// speedup vs baseline: 1.1309x; 1.1309x over previous
#include <cuda_runtime.h>
#include <cuda_bf16.h>
#include <math.h>

// ---------------------------------------------------------------------------
// ModelAndLoss: CE(output, target) + 0.1 * sum of pairwise CKA over two
// feature groups. Output layout: [loss, output(64*1000)] fp32.
//
// Gram kernel: plain scalar-FFMA SGEMM, 128 threads, 8x4 register tile.
// Smem holds 64 column-planes (permuted column order -> conflict-light STS);
// compute reads are aligned LDS.128. Per-block partial tiles -> g_part ->
// reduce -> g_gram. No atomics anywhere.
// ---------------------------------------------------------------------------

#define NROW 64
#define NF   7
#define NBLK 1280               // 768 (A: 3x256 chunks) + 512 (B: 4x128 chunks)

__device__ float g_part[(long long)NBLK * NROW * NROW];  // per-block partial grams
__device__ float g_gram[NF][NROW * NROW];
__device__ float g_ce;

// ---- Gram partial kernel --------------------------------------------------
// Each block owns one (gram, 256-column span) = 4 stages of 64 columns.
// Xs[p][row] = column value; plane p holds global column 4*(p%16) + (p/16)
// within the stage (a fixed permutation -- k-sum order is irrelevant).
__global__ __launch_bounds__(128) void gram_kernel(const float* __restrict__ A,
                                                   const float* __restrict__ B) {
    __shared__ __align__(16) float Xs[64][68];   // 17,408 B

    const int bid = blockIdx.x;
    const float* Xp;
    long long D, c0;
    if (bid < 768) {                       // group A: 3 grams x 256 chunks
        int f  = bid >> 8;
        int ch = bid & 255;
        Xp = A + (long long)f * NROW * 65536;
        D  = 65536; c0 = (long long)ch * 256;
    } else {                               // group B: 4 grams x 128 chunks
        int rel = bid - 768;
        int f  = rel >> 7;
        int ch = rel & 127;
        Xp = B + (long long)f * NROW * 32768;
        D  = 32768; c0 = (long long)ch * 256;
    }

    const int tid = threadIdx.x;
    const int tx = tid & 15, ty = tid >> 4;   // ty 0..7
    const int i0 = ty * 8, j0 = tx * 4;

    float acc[8][4];
    #pragma unroll
    for (int u = 0; u < 8; ++u)
        #pragma unroll
        for (int v = 0; v < 4; ++v) acc[u][v] = 0.0f;

    float4 pre[8];
    // LDG: idx = tid + 128 t -> row = idx>>4 (0..63), q = idx&15 (float4 col)
    // half-warp reads 256 contiguous bytes -> fully coalesced
    #define LDG_STAGE(s)                                                     \
        {                                                                    \
            const long long cs = c0 + (s) * 64;                              \
            _Pragma("unroll")                                                \
            for (int t = 0; t < 8; ++t) {                                    \
                int lin = tid + 128 * t;                                     \
                int row = lin >> 4, q = lin & 15;                            \
                pre[t] = *(const float4*)(Xp + (long long)row * D + cs + 4 * q); \
            }                                                                \
        }
    // STS: component c of quad q -> plane q + 16c (permuted column order).
    // Lanes in a warp hit banks 4q mod 32 (+row offset) -> ~2-way conflicts.
    #define STS_STAGE()                                                      \
        {                                                                    \
            _Pragma("unroll")                                                \
            for (int t = 0; t < 8; ++t) {                                    \
                int lin = tid + 128 * t;                                     \
                int row = lin >> 4, q = lin & 15;                            \
                Xs[q][row]      = pre[t].x;                                  \
                Xs[q + 16][row] = pre[t].y;                                  \
                Xs[q + 32][row] = pre[t].z;                                  \
                Xs[q + 48][row] = pre[t].w;                                  \
            }                                                                \
        }

    LDG_STAGE(0);

    #pragma unroll 1
    for (int s = 0; s < 4; ++s) {
        __syncthreads();                   // prior stage's reads complete
        STS_STAGE();
        __syncthreads();                   // fill visible
        if (s < 3) LDG_STAGE(s + 1);       // prefetch next stage into regs

        #pragma unroll 4
        for (int p = 0; p < 64; ++p) {
            const float4 bv  = *(const float4*)&Xs[p][j0];
            const float4 av0 = *(const float4*)&Xs[p][i0];
            const float4 av1 = *(const float4*)&Xs[p][i0 + 4];
            const float a0 = av0.x, a1 = av0.y, a2 = av0.z, a3 = av0.w;
            const float a4 = av1.x, a5 = av1.y, a6 = av1.z, a7 = av1.w;
            acc[0][0] = fmaf(a0, bv.x, acc[0][0]);
            acc[0][1] = fmaf(a0, bv.y, acc[0][1]);
            acc[0][2] = fmaf(a0, bv.z, acc[0][2]);
            acc[0][3] = fmaf(a0, bv.w, acc[0][3]);
            acc[1][0] = fmaf(a1, bv.x, acc[1][0]);
            acc[1][1] = fmaf(a1, bv.y, acc[1][1]);
            acc[1][2] = fmaf(a1, bv.z, acc[1][2]);
            acc[1][3] = fmaf(a1, bv.w, acc[1][3]);
            acc[2][0] = fmaf(a2, bv.x, acc[2][0]);
            acc[2][1] = fmaf(a2, bv.y, acc[2][1]);
            acc[2][2] = fmaf(a2, bv.z, acc[2][2]);
            acc[2][3] = fmaf(a2, bv.w, acc[2][3]);
            acc[3][0] = fmaf(a3, bv.x, acc[3][0]);
            acc[3][1] = fmaf(a3, bv.y, acc[3][1]);
            acc[3][2] = fmaf(a3, bv.z, acc[3][2]);
            acc[3][3] = fmaf(a3, bv.w, acc[3][3]);
            acc[4][0] = fmaf(a4, bv.x, acc[4][0]);
            acc[4][1] = fmaf(a4, bv.y, acc[4][1]);
            acc[4][2] = fmaf(a4, bv.z, acc[4][2]);
            acc[4][3] = fmaf(a4, bv.w, acc[4][3]);
            acc[5][0] = fmaf(a5, bv.x, acc[5][0]);
            acc[5][1] = fmaf(a5, bv.y, acc[5][1]);
            acc[5][2] = fmaf(a5, bv.z, acc[5][2]);
            acc[5][3] = fmaf(a5, bv.w, acc[5][3]);
            acc[6][0] = fmaf(a6, bv.x, acc[6][0]);
            acc[6][1] = fmaf(a6, bv.y, acc[6][1]);
            acc[6][2] = fmaf(a6, bv.z, acc[6][2]);
            acc[6][3] = fmaf(a6, bv.w, acc[6][3]);
            acc[7][0] = fmaf(a7, bv.x, acc[7][0]);
            acc[7][1] = fmaf(a7, bv.y, acc[7][1]);
            acc[7][2] = fmaf(a7, bv.z, acc[7][2]);
            acc[7][3] = fmaf(a7, bv.w, acc[7][3]);
        }
    }
    #undef LDG_STAGE
    #undef STS_STAGE

    // store 8x4 partial tile (float4 rows, fully coalesced across threads)
    float* P = g_part + (long long)bid * (NROW * NROW);
    #pragma unroll
    for (int u = 0; u < 8; ++u) {
        float4 v = make_float4(acc[u][0], acc[u][1], acc[u][2], acc[u][3]);
        *(float4*)&P[(i0 + u) * NROW + j0] = v;
    }
}

// ---- Reduce partials into g_gram (coalesced, no atomics) ------------------
__global__ void reduce_kernel() {
    int e = blockIdx.x * 256 + threadIdx.x;          // 0 .. 28671
    int f = e >> 12, entry = e & 4095;
    int base, cnt;
    if (f < 3) { base = f * 256;             cnt = 256; }
    else       { base = 768 + (f - 3) * 128; cnt = 128; }
    const float* p = g_part + (long long)base * 4096 + entry;
    float s = 0.0f;
    #pragma unroll 4
    for (int b = 0; b < cnt; ++b) s += p[(long long)b * 4096];
    g_gram[f][entry] = s;
}

// ---- Cross-entropy: single block, warp-per-row, dtype-agnostic target -----
__global__ void ce_kernel(const float* __restrict__ x,
                          const void* __restrict__ tgt_raw) {
    __shared__ float rowloss[NROW];
    __shared__ int is64;
    const int w = threadIdx.x >> 5, lane = threadIdx.x & 31;

    if (threadIdx.x == 0) {
        const int* t32 = (const int*)tgt_raw;
        int odd_or = 0;
        for (int i = 1; i < 64; i += 2) odd_or |= t32[i];
        is64 = (odd_or == 0);
    }
    __syncthreads();

    for (int row = w; row < NROW; row += 8) {
        const float* xr = x + row * 1000;
        float m = -1e30f;
        for (int c = lane; c < 1000; c += 32) m = fmaxf(m, xr[c]);
        for (int off = 16; off; off >>= 1)
            m = fmaxf(m, __shfl_xor_sync(0xffffffffu, m, off));
        float s = 0.0f;
        for (int c = lane; c < 1000; c += 32) s += expf(xr[c] - m);
        for (int off = 16; off; off >>= 1)
            s += __shfl_xor_sync(0xffffffffu, s, off);
        if (lane == 0) {
            int t = is64 ? (int)((const long long*)tgt_raw)[row]
                         : ((const int*)tgt_raw)[row];
            rowloss[row] = (m + logf(s)) - xr[t];
        }
    }
    __syncthreads();
    if (threadIdx.x == 0) {
        float t = 0.0f;
        for (int r = 0; r < NROW; ++r) t += rowloss[r];
        g_ce = t / 64.0f;
    }
}

// ---- Finalize: HSIC/CKA from grams, write loss ----------------------------
__global__ void finalize_kernel(float* __restrict__ dst, int out_size) {
    __shared__ float r[NF][NROW];     // row sums (diag excluded)
    __shared__ double trkl[NF][NF];
    __shared__ double red[256];
    const int tid = threadIdx.x;

    for (int t = tid; t < NF * NROW; t += 256) {
        int f = t / NROW, a = t % NROW;
        const float* G = g_gram[f];
        float s = 0.0f;
        for (int b = 0; b < NROW; ++b)
            if (b != a) s += G[a * NROW + b];
        r[f][a] = s;
    }
    __syncthreads();

    for (int p = 0; p < NF * NF; ++p) {
        int i = p / NF, j = p % NF;
        bool same = (i < 3 && j < 3) || (i >= 3 && j >= 3);
        if (!same || j < i) continue;
        const float* Gi = g_gram[i];
        const float* Gj = g_gram[j];
        double sum = 0.0;
        for (int idx = tid; idx < NROW * NROW; idx += 256) {
            int a = idx >> 6, b = idx & 63;
            if (a != b) sum += (double)Gi[idx] * (double)Gj[idx];
        }
        red[tid] = sum; __syncthreads();
        for (int s = 128; s > 0; s >>= 1) {
            if (tid < s) red[tid] += red[tid + s];
            __syncthreads();
        }
        if (tid == 0) trkl[i][j] = red[0];
        __syncthreads();
    }

    if (tid == 0) {
        double s[NF];
        for (int f = 0; f < NF; ++f) {
            double ss = 0.0;
            for (int a = 0; a < NROW; ++a) ss += (double)r[f][a];
            s[f] = ss;
        }
        auto hsic = [&](int i, int j) -> double {
            double rr = 0.0;
            for (int a = 0; a < NROW; ++a) rr += (double)r[i][a] * (double)r[j][a];
            double t = (i <= j) ? trkl[i][j] : trkl[j][i];
            return (t + s[i] * s[j] / 3906.0 - 2.0 * rr / 62.0) / 3904.0;
        };
        double cka = 0.0;
        double d[NF];
        for (int f = 0; f < NF; ++f) d[f] = sqrt(hsic(f, f));
        for (int i = 0; i < 3; ++i)
            for (int j = 0; j < 3; ++j)
                cka += hsic(i, j) / (d[i] * d[j]);
        for (int i = 3; i < NF; ++i)
            for (int j = 3; j < NF; ++j)
                cka += hsic(i, j) / (d[i] * d[j]);

        float loss = g_ce + 0.1f * (float)cka;
        if (out_size > 64000) dst[0] = loss;
    }
}

// ---- echo the logits into the output buffer -------------------------------
__global__ void copy_kernel(const float* __restrict__ src, float* __restrict__ dst,
                            int n) {
    int i = blockIdx.x * 256 + threadIdx.x;
    if (i < n) dst[i] = src[i];
}

extern "C" void kernel_launch(void* const* d_in, const int* in_sizes, int n_in,
                              void* d_out, int out_size) {
    const float* outp = (const float*)d_in[0];
    const void*  tgt  = (const void*)d_in[1];
    const float* fa   = (const float*)d_in[2];
    const float* fb   = (const float*)d_in[3];
    float* dst = (float*)d_out;

    gram_kernel<<<NBLK, 128>>>(fa, fb);
    reduce_kernel<<<112, 256>>>();
    ce_kernel<<<1, 256>>>(outp, tgt);

    int off = out_size - 64000;
    if (off < 0) off = 0;
    copy_kernel<<<(64000 + 255) / 256, 256>>>(outp, dst + off, 64000);
    finalize_kernel<<<1, 256>>>(dst, out_size);
}